// round 6
// baseline (speedup 1.0000x reference)
#include <cuda_runtime.h>
#include <cuda_fp16.h>
#include <math.h>
#include <stdint.h>

#define NU 100000
#define NI 50000
#define KN 100
#define BB 8192

// Precomputed fp16 tables
__device__ __half g_pe_user[NU * 64];
__device__ __half g_pe_item[NI * 64];
__device__ __half g_uscr16[(size_t)NU * 112];   // scr rows padded to 112, cols 100-111 zero
__device__ __half g_iscr16[(size_t)NI * 112];
__device__ __half g_w2h[64 * 64];
__device__ __half g_w3h[32 * 64];
__device__ __half g_w4h[32 * 32];
__device__ __half g_b2h[64];
__device__ __half g_b3h[32];
__device__ __half g_b4h[32];

// ---------------------------------------------------------------------------
// Main-kernel SMEM (byte offsets):
//   A1 [112 r][232 k-halves] stride 464B @ 0      (51968)
//       - per-warp private act buffers live inside warp w's 16-row block:
//         buf0 @ w*7424, buf1 @ w*7424+2304 (16 rows x 144B each)
//   B1 [224 k][72 n] stride 144B         @ 51968  (32256)
//   W2 [64][72h]  stride 144             @ 84224  (9216)
//   W3 [32][72h]  stride 144             @ 93440  (4608)
//   W4 [32][40h]  stride 80              @ 98048  (2560)
//   MISC (floats)                        @ 100608 (1392)
// Total 102016 B -> 2 CTAs/SM
// ---------------------------------------------------------------------------
#define OFF_A1   0
#define OFF_B1   51968
#define OFF_W2   84224
#define OFF_W3   93440
#define OFF_W4   98048
#define OFF_MISC 100608
#define SMEM_BYTES 102016
// MISC float indices
#define MISC_W5   0
#define MISC_B5   32
#define MISC_RED  36
#define MISC_NIDX 148

#define CP_ASYNC16(dst, src) \
    asm volatile("cp.async.cg.shared.global [%0], [%1], 16;" :: "r"(dst), "l"(src))
#define CP_COMMIT() asm volatile("cp.async.commit_group;" ::: "memory")
#define CP_WAIT0()  asm volatile("cp.async.wait_group 0;" ::: "memory")

__device__ __forceinline__ void ldsm4(uint32_t (&r)[4], uint32_t a) {
    asm volatile("ldmatrix.sync.aligned.m8n8.x4.shared.b16 {%0,%1,%2,%3}, [%4];"
                 : "=r"(r[0]), "=r"(r[1]), "=r"(r[2]), "=r"(r[3]) : "r"(a));
}
__device__ __forceinline__ void ldsm2(uint32_t (&r)[2], uint32_t a) {
    asm volatile("ldmatrix.sync.aligned.m8n8.x2.shared.b16 {%0,%1}, [%2];"
                 : "=r"(r[0]), "=r"(r[1]) : "r"(a));
}
__device__ __forceinline__ void ldsm2t(uint32_t (&r)[2], uint32_t a) {
    asm volatile("ldmatrix.sync.aligned.m8n8.x2.trans.shared.b16 {%0,%1}, [%2];"
                 : "=r"(r[0]), "=r"(r[1]) : "r"(a));
}
__device__ __forceinline__ void mma_f32acc(float (&c)[4], const uint32_t (&a)[4],
                                           const uint32_t (&b)[2]) {
    asm volatile(
        "mma.sync.aligned.m16n8k16.row.col.f32.f16.f16.f32 "
        "{%0,%1,%2,%3}, {%4,%5,%6,%7}, {%8,%9}, {%0,%1,%2,%3};"
        : "+f"(c[0]), "+f"(c[1]), "+f"(c[2]), "+f"(c[3])
        : "r"(a[0]), "r"(a[1]), "r"(a[2]), "r"(a[3]), "r"(b[0]), "r"(b[1]));
}
__device__ __forceinline__ void mma_f16acc(uint32_t (&c)[2], const uint32_t (&a)[4],
                                           const uint32_t (&b)[2]) {
    asm volatile(
        "mma.sync.aligned.m16n8k16.row.col.f16.f16.f16.f16 "
        "{%0,%1}, {%2,%3,%4,%5}, {%6,%7}, {%0,%1};"
        : "+r"(c[0]), "+r"(c[1])
        : "r"(a[0]), "r"(a[1]), "r"(a[2]), "r"(a[3]), "r"(b[0]), "r"(b[1]));
}

__device__ __forceinline__ uint32_t h2_bits(float x, float y) {
    __half2 h = __floats2half2_rn(x, y);
    return *(uint32_t*)&h;
}
__device__ __forceinline__ void cvt_store4(char* dst, float4 v) {
    uint32_t lo = h2_bits(v.x, v.y), hi = h2_bits(v.z, v.w);
    uint2 u; u.x = lo; u.y = hi;
    *(uint2*)dst = u;
}

// ---------------------------------------------------------------------------
// pe_kernel (tensor core): pe[n][o] = fp16(sum_d emb[n][d] * w1[o][w1_off+d])
// 256 rows/block, each warp owns 2 m16 tiles; W1 smem load amortized 2x.
// ---------------------------------------------------------------------------
__global__ __launch_bounds__(256) void pe_kernel(
    const float* __restrict__ emb, const float* __restrict__ w1,
    int w1_off, int which, int nrows)
{
    __shared__ __half W1h[64 * 72];
    __shared__ __half E[256 * 72];
    __half* __restrict__ pe = which ? g_pe_item : g_pe_user;

    const int tid = threadIdx.x;
    const int rows0 = blockIdx.x * 256;

    for (int t = tid; t < 64 * 16; t += 256) {
        int o = t >> 4, k4 = t & 15;
        float4 v = *(const float4*)(w1 + o * 128 + w1_off + k4 * 4);
        cvt_store4((char*)(W1h + o * 72 + k4 * 4), v);
    }
    for (int t = tid; t < 256 * 16; t += 256) {
        int r = t >> 4, k4 = t & 15;
        int n = rows0 + r;
        float4 v = (n < nrows) ? *(const float4*)(emb + (size_t)n * 64 + k4 * 4)
                               : make_float4(0.f, 0.f, 0.f, 0.f);
        cvt_store4((char*)(E + r * 72 + k4 * 4), v);
    }
    __syncthreads();

    const int lane = tid & 31, w = tid >> 5;
    uint32_t sE = (uint32_t)__cvta_generic_to_shared(E);
    uint32_t sW = (uint32_t)__cvta_generic_to_shared(W1h);
    uint32_t aAddr[2];
#pragma unroll
    for (int mt = 0; mt < 2; mt++)
        aAddr[mt] = sE + (uint32_t)(w * 32 + mt * 16 + (lane & 15)) * 144u
                  + (uint32_t)((lane >> 4) << 4);
    uint32_t bAddr0 = sW + (uint32_t)(lane & 7) * 144u + (uint32_t)(((lane >> 3) & 1) << 4);

    float acc[2][8][4];
#pragma unroll
    for (int mt = 0; mt < 2; mt++)
#pragma unroll
        for (int nt = 0; nt < 8; nt++)
#pragma unroll
            for (int i = 0; i < 4; i++) acc[mt][nt][i] = 0.f;

#pragma unroll
    for (int ks = 0; ks < 4; ks++) {
        uint32_t a[2][4];
        ldsm4(a[0], aAddr[0] + ks * 32);
        ldsm4(a[1], aAddr[1] + ks * 32);
#pragma unroll
        for (int nt = 0; nt < 8; nt++) {
            uint32_t b[2];
            ldsm2(b, bAddr0 + (uint32_t)nt * 8u * 144u + ks * 32);
            mma_f32acc(acc[0][nt], a[0], b);
            mma_f32acc(acc[1][nt], a[1], b);
        }
    }

    int c0 = (lane & 3) * 2;
#pragma unroll
    for (int mt = 0; mt < 2; mt++) {
        int r0 = rows0 + w * 32 + mt * 16 + (lane >> 2);
#pragma unroll
        for (int nt = 0; nt < 8; nt++) {
            int col = nt * 8 + c0;
            if (r0 < nrows)
                *(__half2*)(pe + (size_t)r0 * 64 + col) =
                    __floats2half2_rn(acc[mt][nt][0], acc[mt][nt][1]);
            if (r0 + 8 < nrows)
                *(__half2*)(pe + (size_t)(r0 + 8) * 64 + col) =
                    __floats2half2_rn(acc[mt][nt][2], acc[mt][nt][3]);
        }
    }
}

// ---------------------------------------------------------------------------
// scr_cvt: fp32 scr [nrows][100] -> fp16 padded [nrows][112]
// ---------------------------------------------------------------------------
__global__ __launch_bounds__(256) void scr_cvt_kernel(
    const float* __restrict__ src, int which, int nrows)
{
    __half* __restrict__ dst = which ? g_iscr16 : g_uscr16;
    int total = nrows * 14;
    for (int t = blockIdx.x * 256 + threadIdx.x; t < total; t += gridDim.x * 256) {
        int n = t / 14, cb = t % 14;
        uint32_t o[4] = {0, 0, 0, 0};
        if (cb < 12) {
            float4 a = *(const float4*)(src + (size_t)n * 100 + cb * 8);
            float4 bq = *(const float4*)(src + (size_t)n * 100 + cb * 8 + 4);
            o[0] = h2_bits(a.x, a.y);  o[1] = h2_bits(a.z, a.w);
            o[2] = h2_bits(bq.x, bq.y); o[3] = h2_bits(bq.z, bq.w);
        } else if (cb == 12) {
            float4 a = *(const float4*)(src + (size_t)n * 100 + 96);
            o[0] = h2_bits(a.x, a.y);  o[1] = h2_bits(a.z, a.w);
        }
        uint4 v; v.x = o[0]; v.y = o[1]; v.z = o[2]; v.w = o[3];
        *(uint4*)(dst + (size_t)n * 112 + cb * 8) = v;
    }
}

__global__ __launch_bounds__(256) void wcvt_kernel(
    const float* __restrict__ w2, const float* __restrict__ w3,
    const float* __restrict__ w4, const float* __restrict__ b2,
    const float* __restrict__ b3, const float* __restrict__ b4)
{
    int t = blockIdx.x * 256 + threadIdx.x;
    if (t < 4096) g_w2h[t] = __float2half_rn(w2[t]);
    else if (t < 6144) g_w3h[t - 4096] = __float2half_rn(w3[t - 4096]);
    else if (t < 7168) g_w4h[t - 6144] = __float2half_rn(w4[t - 6144]);
    else if (t < 7232) g_b2h[t - 7168] = __float2half_rn(b2[t - 7168]);
    else if (t < 7264) g_b3h[t - 7232] = __float2half_rn(b3[t - 7232]);
    else if (t < 7296) g_b4h[t - 7264] = __float2half_rn(b4[t - 7264]);
}

// ---------------------------------------------------------------------------
// Per-warp f16-acc layer: A = warp-private tile [16][K] stride 144,
// B = weights [N][K] n-major, out (if cAddr) relu(+bias) to stride-144 tile.
// ---------------------------------------------------------------------------
template <int KS, int NT, int BSTR>
__device__ __forceinline__ void warp_layer(
    uint32_t aAddr, uint32_t bBase, uint32_t cAddr,
    const __half* __restrict__ bias, int lane, uint32_t (*accOut)[2])
{
    uint32_t bAddr[NT];
#pragma unroll
    for (int nt = 0; nt < NT; nt++)
        bAddr[nt] = bBase + (uint32_t)(nt * 8 + (lane & 7)) * BSTR
                  + (uint32_t)(((lane >> 3) & 1) << 4);

    uint32_t acc[NT][2];
#pragma unroll
    for (int nt = 0; nt < NT; nt++) { acc[nt][0] = 0u; acc[nt][1] = 0u; }

#pragma unroll
    for (int ks = 0; ks < KS; ks++) {
        uint32_t a[4];
        ldsm4(a, aAddr + ks * 32);
#pragma unroll
        for (int nt = 0; nt < NT; nt++) {
            uint32_t b[2];
            ldsm2(b, bAddr[nt] + ks * 32);
            mma_f16acc(acc[nt], a, b);
        }
    }

    const int r = lane >> 2, cc = (lane & 3) * 2;
    const __half2 z = __floats2half2_rn(0.f, 0.f);
    if (accOut) {
#pragma unroll
        for (int nt = 0; nt < NT; nt++) {
            __half2 b2v = *(const __half2*)(bias + nt * 8 + cc);
            __half2 v0 = __hmax2(__hadd2(*(__half2*)&acc[nt][0], b2v), z);
            __half2 v1 = __hmax2(__hadd2(*(__half2*)&acc[nt][1], b2v), z);
            accOut[nt][0] = *(uint32_t*)&v0;
            accOut[nt][1] = *(uint32_t*)&v1;
        }
    } else {
#pragma unroll
        for (int nt = 0; nt < NT; nt++) {
            __half2 b2v = *(const __half2*)(bias + nt * 8 + cc);
            __half2 v0 = __hmax2(__hadd2(*(__half2*)&acc[nt][0], b2v), z);
            __half2 v1 = __hmax2(__hadd2(*(__half2*)&acc[nt][1], b2v), z);
            *(uint32_t*)((char*)0 + cAddr + r * 144 + (nt * 8 + cc) * 2) = *(uint32_t*)&v0;   // unused path
            *(uint32_t*)((char*)0 + cAddr + (r + 8) * 144 + (nt * 8 + cc) * 2) = *(uint32_t*)&v1;
        }
    }
}

// ---------------------------------------------------------------------------
__global__ __launch_bounds__(256, 2) void cnn_main_kernel(
    const float* __restrict__ b1g,
    const float* __restrict__ w5g, const float* __restrict__ b5g,
    const int* __restrict__ uidxT, const int* __restrict__ iidxT,
    const int* __restrict__ uidxs, const int* __restrict__ iidxs,
    float* __restrict__ out)
{
    extern __shared__ char smb[];
    float* misc = (float*)(smb + OFF_MISC);
    int* nidx = (int*)(misc + MISC_NIDX);
    uint32_t sbase = (uint32_t)__cvta_generic_to_shared(smb);
    const int tid = threadIdx.x;
    const int b = blockIdx.x;

    // Phase 0: neighbor indices, w5/b5, zero B1 pad rows (k 100-111, 212-223)
    if (tid < 200) {
        nidx[tid] = (tid < 100) ? uidxT[(size_t)uidxs[b] * KN + tid]
                                : iidxT[(size_t)iidxs[b] * KN + (tid - 100)];
    } else if (tid < 232) {
        misc[MISC_W5 + tid - 200] = w5g[tid - 200];
    } else if (tid == 232) {
        misc[MISC_B5] = b5g[0];
    }
    if (tid < 192) {
        int rr = tid >> 3;
        int row = (rr < 12) ? 100 + rr : 200 + rr;
        *(uint4*)(smb + OFF_B1 + row * 144 + (tid & 7) * 16) = make_uint4(0, 0, 0, 0);
    }
    __syncthreads();

    // Phase 1: all gathers via cp.async (16B chunks)
    for (int t = tid; t < 2800; t += 256) {
        int r = t / 28, c = t % 28;
        const char* src = (c < 14)
            ? (const char*)(g_uscr16 + (size_t)nidx[r] * 112) + c * 16
            : (const char*)(g_iscr16 + (size_t)nidx[100 + r] * 112) + (c - 14) * 16;
        CP_ASYNC16(sbase + OFF_A1 + (uint32_t)(r * 464 + c * 16), src);
    }
    for (int t = tid; t < 1600; t += 256) {
        int j = t >> 3, c = t & 7;
        const char* src = (j < 100)
            ? (const char*)(g_pe_user + (size_t)nidx[j] * 64) + c * 16
            : (const char*)(g_pe_item + (size_t)nidx[j] * 64) + c * 16;
        int dr = (j < 100) ? j : j + 12;
        CP_ASYNC16(sbase + OFF_B1 + (uint32_t)(dr * 144 + c * 16), src);
    }
    for (int t = tid; t < 512; t += 256) {
        int o = t >> 3, c = t & 7;
        CP_ASYNC16(sbase + OFF_W2 + (uint32_t)(o * 144 + c * 16),
                   (const char*)(g_w2h + o * 64 + c * 8));
    }
    if (tid < 256) {
        int o = tid >> 3, c = tid & 7;
        CP_ASYNC16(sbase + OFF_W3 + (uint32_t)(o * 144 + c * 16),
                   (const char*)(g_w3h + o * 64 + c * 8));
    }
    if (tid < 128) {
        int o = tid >> 2, c = tid & 3;
        CP_ASYNC16(sbase + OFF_W4 + (uint32_t)(o * 80 + c * 16),
                   (const char*)(g_w4h + o * 32 + c * 8));
    }
    CP_COMMIT();
    CP_WAIT0();
    __syncthreads();   // sync #1: all tiles resident

    const int lane = tid & 31, w = tid >> 5;

    if (w < 7) {
        // Per-warp private buffers inside this warp's 16-row A1 block
        const uint32_t buf0 = sbase + OFF_A1 + (uint32_t)w * 7424u;
        const uint32_t buf1 = buf0 + 2304u;
        const int r = lane >> 2, cc = (lane & 3) * 2;

        // ---- GEMM1 (fp32 acc): rows w*16.., all 64 cols, K=224 ----
        {
            uint32_t aAddr = sbase + OFF_A1
                           + (uint32_t)(w * 16 + (lane & 15)) * 464u
                           + (uint32_t)((lane >> 4) << 4);
            uint32_t bAddr = sbase + OFF_B1 + (uint32_t)(lane & 15) * 144u;

            float acc[8][4];
#pragma unroll
            for (int nt = 0; nt < 8; nt++)
#pragma unroll
                for (int i = 0; i < 4; i++) acc[nt][i] = 0.f;

#pragma unroll
            for (int ks = 0; ks < 14; ks++) {
                uint32_t a[4];
                ldsm4(a, aAddr + ks * 32);
#pragma unroll
                for (int nt = 0; nt < 8; nt++) {
                    uint32_t bq[2];
                    ldsm2t(bq, bAddr + (uint32_t)(nt << 4) + ks * 2304);
                    mma_f32acc(acc[nt], a, bq);
                }
            }
            // epilogue -> buf0 (overwrites this warp's own A rows; safe)
#pragma unroll
            for (int nt = 0; nt < 8; nt++) {
                int col = nt * 8 + cc;
                float bx = b1g[col], by = b1g[col + 1];
                *(uint32_t*)(smb + (buf0 - sbase) + r * 144 + col * 2) =
                    h2_bits(fmaxf(acc[nt][0] + bx, 0.f), fmaxf(acc[nt][1] + by, 0.f));
                *(uint32_t*)(smb + (buf0 - sbase) + (r + 8) * 144 + col * 2) =
                    h2_bits(fmaxf(acc[nt][2] + bx, 0.f), fmaxf(acc[nt][3] + by, 0.f));
            }
        }
        __syncwarp();

        // ---- L2 (f16 acc): K=64, N=64, buf0 -> buf1 ----
        {
            uint32_t aAddr = buf0 + (uint32_t)(lane & 15) * 144u + (uint32_t)((lane >> 4) << 4);
            uint32_t acc2[8][2];
            warp_layer<4, 8, 144>(aAddr, sbase + OFF_W2, 0, g_b2h, lane, acc2);
#pragma unroll
            for (int nt = 0; nt < 8; nt++) {
                int col = nt * 8 + cc;
                *(uint32_t*)(smb + (buf1 - sbase) + r * 144 + col * 2) = acc2[nt][0];
                *(uint32_t*)(smb + (buf1 - sbase) + (r + 8) * 144 + col * 2) = acc2[nt][1];
            }
        }
        __syncwarp();

        // ---- L3 (f16 acc): K=64, N=32, buf1 -> buf0 ----
        {
            uint32_t aAddr = buf1 + (uint32_t)(lane & 15) * 144u + (uint32_t)((lane >> 4) << 4);
            uint32_t acc3[4][2];
            warp_layer<4, 4, 144>(aAddr, sbase + OFF_W3, 0, g_b3h, lane, acc3);
#pragma unroll
            for (int nt = 0; nt < 4; nt++) {
                int col = nt * 8 + cc;
                *(uint32_t*)(smb + (buf0 - sbase) + r * 144 + col * 2) = acc3[nt][0];
                *(uint32_t*)(smb + (buf0 - sbase) + (r + 8) * 144 + col * 2) = acc3[nt][1];
            }
        }
        __syncwarp();

        // ---- L4 (f16 acc): K=32, N=32, buf0 -> regs; L5 in regs ----
        {
            uint32_t aAddr = buf0 + (uint32_t)(lane & 15) * 144u + (uint32_t)((lane >> 4) << 4);
            uint32_t acc4[4][2];
            warp_layer<2, 4, 80>(aAddr, sbase + OFF_W4, 0, g_b4h, lane, acc4);

            // L5: s = sum_col relu-ed h4 * w5  (acc4 already relu(+b4))
            float s0 = 0.f, s1 = 0.f;
#pragma unroll
            for (int nt = 0; nt < 4; nt++) {
                int col = nt * 8 + cc;
                float2 f0 = __half22float2(*(__half2*)&acc4[nt][0]);
                float2 f1 = __half22float2(*(__half2*)&acc4[nt][1]);
                float wx = misc[MISC_W5 + col], wy = misc[MISC_W5 + col + 1];
                s0 += f0.x * wx + f0.y * wy;
                s1 += f1.x * wx + f1.y * wy;
            }
            // reduce across the 4 lanes of this row-quad
            s0 += __shfl_xor_sync(0xffffffffu, s0, 1);
            s0 += __shfl_xor_sync(0xffffffffu, s0, 2);
            s1 += __shfl_xor_sync(0xffffffffu, s1, 1);
            s1 += __shfl_xor_sync(0xffffffffu, s1, 2);
            if ((lane & 3) == 0) {
                int row0 = w * 16 + r, row1 = row0 + 8;
                float bb = misc[MISC_B5];
                misc[MISC_RED + row0] =
                    (row0 < 100) ? 1.f / (1.f + __expf(-(s0 + bb))) : 0.f;
                misc[MISC_RED + row1] =
                    (row1 < 100) ? 1.f / (1.f + __expf(-(s1 + bb))) : 0.f;
            }
        }
    }
    __syncthreads();   // sync #2: RED complete

    if (tid < 32) {
        float v = misc[MISC_RED + tid] + misc[MISC_RED + tid + 32]
                + misc[MISC_RED + tid + 64]
                + ((tid < 16) ? misc[MISC_RED + tid + 96] : 0.f);
#pragma unroll
        for (int off = 16; off; off >>= 1)
            v += __shfl_down_sync(0xffffffffu, v, off);
        if (tid == 0) out[b] = v * (1.f / 100.f);
    }
}

// ---------------------------------------------------------------------------
extern "C" void kernel_launch(void* const* d_in, const int* in_sizes, int n_in,
                              void* d_out, int out_size)
{
    const float* user_emb = (const float*)d_in[0];
    const float* item_emb = (const float*)d_in[1];
    const float* user_scr = (const float*)d_in[2];
    const float* item_scr = (const float*)d_in[3];
    const float* w1 = (const float*)d_in[4];
    const float* b1 = (const float*)d_in[5];
    const float* w2 = (const float*)d_in[6];
    const float* b2 = (const float*)d_in[7];
    const float* w3 = (const float*)d_in[8];
    const float* b3 = (const float*)d_in[9];
    const float* w4 = (const float*)d_in[10];
    const float* b4 = (const float*)d_in[11];
    const float* w5 = (const float*)d_in[12];
    const float* b5 = (const float*)d_in[13];
    const int* user_idx_tensor = (const int*)d_in[14];
    const int* item_idx_tensor = (const int*)d_in[15];
    const int* user_idxs = (const int*)d_in[16];
    const int* item_idxs = (const int*)d_in[17];
    float* out = (float*)d_out;

    pe_kernel<<<(NU + 255) / 256, 256>>>(user_emb, w1, 0, 0, NU);
    pe_kernel<<<(NI + 255) / 256, 256>>>(item_emb, w1, 64, 1, NI);
    scr_cvt_kernel<<<(NU * 14 + 255) / 256, 256>>>(user_scr, 0, NU);
    scr_cvt_kernel<<<(NI * 14 + 255) / 256, 256>>>(item_scr, 1, NI);
    wcvt_kernel<<<29, 256>>>(w2, w3, w4, b2, b3, b4);

    cudaFuncSetAttribute(cnn_main_kernel,
                         cudaFuncAttributeMaxDynamicSharedMemorySize, SMEM_BYTES);
    cnn_main_kernel<<<BB, 256, SMEM_BYTES>>>(
        b1, w5, b5,
        user_idx_tensor, item_idx_tensor, user_idxs, item_idxs,
        out);
}